// round 12
// baseline (speedup 1.0000x reference)
#include <cuda_runtime.h>
#include <cuda_bf16.h>
#include <cstdint>

// ---------------------------------------------------------------------------
// STDP as two K=T*B GEMMs on mma.sync (bf16, fp32 accumulate).
// Scan parallelized over time via chunked linear-recurrence decomposition.
//   M1[o][i] = sum_k post_s[k][o] * pre_trH[k][i]   (post_s exact in bf16)
//   M2[o][i] = sum_k post_trH[k][o] * pre_s[k][i]   (pre_s  exact in bf16)
//   dw = LR_LTP*(1-w)*M1/B + LR_LTD*w*M2/B
// GEMM: 128-thr CTAs, warp tile 64x64, fragment double-buffering across kk.
// Split-K reduce fused into the GEMM tail (threadfence reduction): the 8th
// producer CTA of each 128x128 tile reduces it from L2-hot partials.
// ---------------------------------------------------------------------------

#define T_STEPS 100
#define BATCH   32
#define NIN     1024
#define NOUT    512
#define KTOT    3200                 // k = t*32 + b
#define KSPLIT  4
#define KPER    800                  // KTOT / KSPLIT
#define KC      80                   // k rows per smem stage (5 x k16)
#define NSTAGE  10                   // KPER / KC

#define CHUNKS  10
#define CLEN    10                   // T_STEPS / CHUNKS
#define NELEM   (BATCH * (NIN + NOUT))   // 49152 flat scan elements

#define DECAY   0.9512294245007141f  // expf(-1/20)
#define DECAY10 0.6065306597126334f  // expf(-0.5) = DECAY^10
#define LR_LTP  1e-4f
#define LR_LTD  (-1e-4f)

#define TILE_B  20480                // KC(80) rows x 256B (128 bf16 cols)
#define BUF_B   (2 * TILE_B)         // 40KB per stage (A tile + B tile)
#define DSMEM_B (2 * BUF_B)          // 80KB -> 2 CTAs/SM (160KB of 228KB)

// Scratch in natural [k][n] layout (__device__ globals; no allocs allowed)
__device__ __nv_bfloat16 g_preS [KTOT * NIN];    // pre_s  exact bf16
__device__ __nv_bfloat16 g_preH [KTOT * NIN];    // pre_tr bf16
__device__ __nv_bfloat16 g_postS[KTOT * NOUT];   // post_s exact bf16
__device__ __nv_bfloat16 g_postH[KTOT * NOUT];   // post_tr bf16
__device__ float g_f[CHUNKS * NELEM];            // per-chunk local finals
__device__ float g_m1[KSPLIT * NOUT * NIN];      // K-split partials
__device__ float g_m2[KSPLIT * NOUT * NIN];
__device__ unsigned int g_cnt[32];               // per-(x,y)-tile arrivals

// ---------------------------------------------------------------------------
__device__ __forceinline__ uint32_t smem_u32(const void* p) {
    uint32_t a;
    asm("{ .reg .u64 t; cvta.to.shared.u64 t, %1; cvt.u32.u64 %0, t; }"
        : "=r"(a) : "l"(p));
    return a;
}
__device__ __forceinline__ void cp_async16(uint32_t dst, const void* src) {
    asm volatile("cp.async.cg.shared.global [%0], [%1], 16;"
                 :: "r"(dst), "l"(src) : "memory");
}
__device__ __forceinline__ void cp_commit() {
    asm volatile("cp.async.commit_group;" ::: "memory");
}
template <int N> __device__ __forceinline__ void cp_wait() {
    asm volatile("cp.async.wait_group %0;" :: "n"(N) : "memory");
}
__device__ __forceinline__ void ldsm_x4_t(uint32_t& r0, uint32_t& r1,
                                          uint32_t& r2, uint32_t& r3, uint32_t a) {
    asm volatile("ldmatrix.sync.aligned.m8n8.x4.trans.shared.b16 {%0,%1,%2,%3}, [%4];"
                 : "=r"(r0), "=r"(r1), "=r"(r2), "=r"(r3) : "r"(a));
}
__device__ __forceinline__ void mma16816(float* c, const uint32_t* a,
                                         const uint32_t* b) {
    asm volatile(
        "mma.sync.aligned.m16n8k16.row.col.f32.bf16.bf16.f32 "
        "{%0,%1,%2,%3}, {%4,%5,%6,%7}, {%8,%9}, {%0,%1,%2,%3};"
        : "+f"(c[0]), "+f"(c[1]), "+f"(c[2]), "+f"(c[3])
        : "r"(a[0]), "r"(a[1]), "r"(a[2]), "r"(a[3]), "r"(b[0]), "r"(b[1]));
}
__device__ __forceinline__ uint32_t bits_bf2(__nv_bfloat162 v) {
    return *reinterpret_cast<uint32_t*>(&v);
}

// Shared (b, n4) mapping for the scan passes: 48 sub-blocks cover all elems.
struct ScanMap {
    const float* src;
    size_t nb;        // b*N + n4 within src
    size_t stride;    // 32*N
    int flat;         // flat element index (pre first, then post)
    int N, b, n4;
    bool isPre;
};
__device__ __forceinline__ ScanMap scan_map(int sub, int tid,
                                            const float* pre_s,
                                            const float* post_s) {
    ScanMap m;
    if (sub < 32) {
        m.isPre = true; m.N = NIN; m.b = sub; m.n4 = tid * 4;
        m.src = pre_s;
        m.flat = m.b * NIN + m.n4;
    } else {
        m.isPre = false; m.N = NOUT;
        m.b = (sub - 32) * 2 + (tid >> 7); m.n4 = (tid & 127) * 4;
        m.src = post_s;
        m.flat = BATCH * NIN + m.b * NOUT + m.n4;
    }
    m.nb = (size_t)m.b * m.N + m.n4;
    m.stride = (size_t)32 * m.N;
    return m;
}

// ---------------------------------------------------------------------------
// Pass A: per-chunk local scan (zero init) -> g_f[c][elem]; emit bf16 spikes.
// Also resets the per-tile arrival counters for the fused GEMM reduce.
// ---------------------------------------------------------------------------
__global__ void __launch_bounds__(256)
stdp_scanA(const float* __restrict__ pre_s, const float* __restrict__ post_s) {
    if (blockIdx.x == 0 && threadIdx.x < 32) g_cnt[threadIdx.x] = 0;

    const int c   = blockIdx.x / 48;
    const int sub = blockIdx.x % 48;
    const ScanMap m = scan_map(sub, threadIdx.x, pre_s, post_s);
    __nv_bfloat16* gs = m.isPre ? g_preS : g_postS;

    float4 s[CLEN];
    #pragma unroll
    for (int u = 0; u < CLEN; u++)
        s[u] = *(const float4*)(m.src + (size_t)(c * CLEN + u) * m.stride + m.nb);

    float4 tr = make_float4(0.f, 0.f, 0.f, 0.f);
    #pragma unroll
    for (int u = 0; u < CLEN; u++) {
        tr.x = fmaf(tr.x, DECAY, s[u].x);
        tr.y = fmaf(tr.y, DECAY, s[u].y);
        tr.z = fmaf(tr.z, DECAY, s[u].z);
        tr.w = fmaf(tr.w, DECAY, s[u].w);

        uint2 sv;
        sv.x = bits_bf2(__float22bfloat162_rn(make_float2(s[u].x, s[u].y)));
        sv.y = bits_bf2(__float22bfloat162_rn(make_float2(s[u].z, s[u].w)));
        *(uint2*)(gs + (size_t)(c * CLEN + u) * m.stride + m.nb) = sv;
    }
    *(float4*)(g_f + (size_t)c * NELEM + m.flat) = tr;
}

// ---------------------------------------------------------------------------
// Pass C: recombine start from g_f (same fmaf order as a serial pass B ->
// bit-identical), re-scan the chunk, emit bf16 traces + final fp32 traces.
// ---------------------------------------------------------------------------
__global__ void __launch_bounds__(256)
stdp_scanC(const float* __restrict__ pre_s, const float* __restrict__ post_s,
           const float* __restrict__ pre0, const float* __restrict__ post0,
           float* __restrict__ out) {
    const int c   = blockIdx.x / 48;
    const int sub = blockIdx.x % 48;
    const ScanMap m = scan_map(sub, threadIdx.x, pre_s, post_s);
    __nv_bfloat16* gh = m.isPre ? g_preH : g_postH;

    float4 s[CLEN];
    #pragma unroll
    for (int u = 0; u < CLEN; u++)
        s[u] = *(const float4*)(m.src + (size_t)(c * CLEN + u) * m.stride + m.nb);

    // start(c) = fold of initial trace + chunk finals 0..c-1
    float4 tr = m.isPre ? *(const float4*)(pre0 + m.nb)
                        : *(const float4*)(post0 + m.nb);
    #pragma unroll 1
    for (int j = 0; j < c; j++) {
        float4 f = *(const float4*)(g_f + (size_t)j * NELEM + m.flat);
        tr.x = fmaf(tr.x, DECAY10, f.x);
        tr.y = fmaf(tr.y, DECAY10, f.y);
        tr.z = fmaf(tr.z, DECAY10, f.z);
        tr.w = fmaf(tr.w, DECAY10, f.w);
    }

    #pragma unroll
    for (int u = 0; u < CLEN; u++) {
        tr.x = fmaf(tr.x, DECAY, s[u].x);
        tr.y = fmaf(tr.y, DECAY, s[u].y);
        tr.z = fmaf(tr.z, DECAY, s[u].z);
        tr.w = fmaf(tr.w, DECAY, s[u].w);

        uint2 hv;
        hv.x = bits_bf2(__float22bfloat162_rn(make_float2(tr.x, tr.y)));
        hv.y = bits_bf2(__float22bfloat162_rn(make_float2(tr.z, tr.w)));
        *(uint2*)(gh + (size_t)(c * CLEN + u) * m.stride + m.nb) = hv;
    }
    if (c == CHUNKS - 1) {
        const int outoff = NOUT * NIN + (m.isPre ? 0 : BATCH * NIN);
        *(float4*)(out + outoff + m.nb) = tr;
    }
}

// ---------------------------------------------------------------------------
// Kernel 2: mma.sync dual GEMM + fused split-K reduce.
//   blockIdx.z: z%2 = matrix select (0->M1, 1->M2), z/2 = K-slab.
// 128 threads, 4 warps of 64(o)x64(i), fragment double-buffering across kk.
// Tail: 8th arriving producer of tile (x,y) reduces the tile from L2-hot
// partials (same arithmetic order as the old stdp_final -> bit-identical).
// ---------------------------------------------------------------------------
__device__ __forceinline__ void load_tile(uint32_t sdst,
                                          const __nv_bfloat16* __restrict__ src,
                                          int N, int n0, int k0, int tid) {
    #pragma unroll
    for (int it = 0; it < 10; it++) {
        int idx = tid + it * 128;            // 1280 chunks of 16B
        int r = idx >> 4, c = idx & 15;
        uint32_t off = (uint32_t)(r * 256 + c * 16);
        uint32_t sw = off ^ (((uint32_t)r & 7) << 4);
        cp_async16(sdst + sw, src + (size_t)(k0 + r) * N + n0 + c * 8);
    }
}

#define LD_A(dst, buf, kk)                                               \
    { uint32_t koff_ = laneconst + (uint32_t)((kk) * 4096);              \
      _Pragma("unroll")                                                  \
      for (int mt_ = 0; mt_ < 4; mt_++) {                                \
        uint32_t off_ = koff_ + (uint32_t)((wm * 64 + mt_ * 16) * 2);    \
        ldsm_x4_t((dst)[mt_][0], (dst)[mt_][1], (dst)[mt_][2],           \
                  (dst)[mt_][3], (buf) + (off_ ^ xmask));                \
      } }

#define LD_B(dst, buf, kk)                                               \
    { uint32_t koff_ = laneconst + (uint32_t)((kk) * 4096) + TILE_B;     \
      _Pragma("unroll")                                                  \
      for (int ng_ = 0; ng_ < 4; ng_++) {                                \
        uint32_t off_ = koff_ + (uint32_t)((wn * 64 + ng_ * 16) * 2);    \
        uint32_t t0_, t1_, t2_, t3_;                                     \
        ldsm_x4_t(t0_, t1_, t2_, t3_, (buf) + (off_ ^ xmask));           \
        (dst)[ng_ * 2 + 0][0] = t0_; (dst)[ng_ * 2 + 1][0] = t1_;        \
        (dst)[ng_ * 2 + 0][1] = t2_; (dst)[ng_ * 2 + 1][1] = t3_;        \
      } }

__global__ void __launch_bounds__(128, 2)
stdp_gemm_mma(const float* __restrict__ w, float* __restrict__ out) {
    extern __shared__ __align__(1024) char dsm[];
    const uint32_t sb = smem_u32(dsm);

    const int tid  = threadIdx.x;
    const int lane = tid & 31;
    const int wid  = tid >> 5;
    const int wm   = wid >> 1;           // 0..1 -> 64 o-rows
    const int wn   = wid & 1;            // 0..1 -> 64 i-cols
    const int i0   = blockIdx.x * 128;
    const int o0   = blockIdx.y * 128;
    const int gsel = blockIdx.z % 2;
    const int ksl  = blockIdx.z / 2;
    const int kb   = ksl * KPER;
    const int tile = blockIdx.y * 8 + blockIdx.x;

    // M1: A=post_s (exact), B=pre_trH.   M2: A=post_trH, B=pre_s (exact).
    const __nv_bfloat16* Ap = gsel ? g_postH : g_postS;   // [k][NOUT]
    const __nv_bfloat16* Bp = gsel ? g_preS  : g_preH;    // [k][NIN]

    float acc[4][8][4];
    #pragma unroll
    for (int mt = 0; mt < 4; mt++)
        #pragma unroll
        for (int nt = 0; nt < 8; nt++)
            #pragma unroll
            for (int r = 0; r < 4; r++) acc[mt][nt][r] = 0.f;

    load_tile(sb + 0 * TILE_B, Ap, NOUT, o0, kb, tid);
    load_tile(sb + 1 * TILE_B, Bp, NIN,  i0, kb, tid);
    cp_commit();

    // per-lane ldmatrix.trans addressing:
    // row = kk*16 + (lane>>4)*8 + (lane&7); colb = col*2 + ((lane>>3)&1)*16
    const uint32_t laneconst = (uint32_t)(((lane >> 4) * 8 + (lane & 7)) * 256
                                          + ((lane >> 3) & 1) * 16);
    const uint32_t xmask = (uint32_t)((lane & 7) << 4);

    uint32_t afr[2][4][4];               // double-buffered A fragments
    uint32_t bfr[2][8][2];               // double-buffered B fragments

    #pragma unroll 1
    for (int s = 0; s < NSTAGE; s++) {
        if (s + 1 < NSTAGE) {
            uint32_t nbuf = sb + ((s + 1) & 1) * BUF_B;
            int k0 = kb + (s + 1) * KC;
            load_tile(nbuf + 0 * TILE_B, Ap, NOUT, o0, k0, tid);
            load_tile(nbuf + 1 * TILE_B, Bp, NIN,  i0, k0, tid);
            cp_commit();
            cp_wait<1>();
        } else {
            cp_wait<0>();
        }
        __syncthreads();

        const uint32_t buf = sb + (s & 1) * BUF_B;
        LD_A(afr[0], buf, 0);
        LD_B(bfr[0], buf, 0);
        #pragma unroll
        for (int kk = 0; kk < 5; kk++) {
            const int cur = kk & 1;
            const int nxt = cur ^ 1;
            if (kk < 4) {                 // prefetch kk+1 before MMAs of kk
                LD_A(afr[nxt], buf, kk + 1);
                LD_B(bfr[nxt], buf, kk + 1);
            }
            #pragma unroll
            for (int mt = 0; mt < 4; mt++)
                #pragma unroll
                for (int nt = 0; nt < 8; nt++)
                    mma16816(acc[mt][nt], afr[cur][mt], bfr[cur][nt]);
        }
        __syncthreads();
    }

    // epilogue: direct fp32 stores of this slab's partials
    float* gdst = (gsel ? g_m2 : g_m1) + (size_t)ksl * (NOUT * NIN);
    const int rr = lane >> 2;
    const int cc = (lane & 3) * 2;
    #pragma unroll
    for (int mt = 0; mt < 4; mt++) {
        #pragma unroll
        for (int nt = 0; nt < 8; nt++) {
            int row = o0 + wm * 64 + mt * 16 + rr;
            int col = i0 + wn * 64 + nt * 8 + cc;
            float2 v0 = make_float2(acc[mt][nt][0], acc[mt][nt][1]);
            float2 v1 = make_float2(acc[mt][nt][2], acc[mt][nt][3]);
            *(float2*)&gdst[(size_t)row * NIN + col]       = v0;
            *(float2*)&gdst[(size_t)(row + 8) * NIN + col] = v1;
        }
    }

    // ---- fused split-K reduce (threadfence reduction) ----
    __shared__ unsigned int s_old;
    __threadfence();
    __syncthreads();                      // all stores of this CTA issued
    if (tid == 0) s_old = atomicAdd(&g_cnt[tile], 1);
    __syncthreads();
    if (s_old != 7) return;               // not the last producer of the tile
    __threadfence();

    // Reduce this 128x128 tile: identical order/expression to old stdp_final.
    const int n4 = NOUT * NIN / 4;
    const float sp = LR_LTP / (float)BATCH;
    const float sd = LR_LTD / (float)BATCH;
    const int row = tid;                  // 128 threads, one row each
    const int base4 = ((o0 + row) * NIN + i0) >> 2;
    #pragma unroll 4
    for (int c = 0; c < 32; c++) {
        const int idx = base4 + c;
        float4 m1 = make_float4(0.f, 0.f, 0.f, 0.f);
        float4 m2 = make_float4(0.f, 0.f, 0.f, 0.f);
        #pragma unroll
        for (int z = 0; z < KSPLIT; z++) {
            float4 a = ((const float4*)g_m1)[(size_t)z * n4 + idx];
            float4 b = ((const float4*)g_m2)[(size_t)z * n4 + idx];
            m1.x += a.x; m1.y += a.y; m1.z += a.z; m1.w += a.w;
            m2.x += b.x; m2.y += b.y; m2.z += b.z; m2.w += b.w;
        }
        const float4 wv = ((const float4*)w)[idx];
        float4 r;
        r.x = sp * (1.f - wv.x) * m1.x + sd * wv.x * m2.x;
        r.y = sp * (1.f - wv.y) * m1.y + sd * wv.y * m2.y;
        r.z = sp * (1.f - wv.z) * m1.z + sd * wv.z * m2.z;
        r.w = sp * (1.f - wv.w) * m1.w + sd * wv.w * m2.w;
        ((float4*)out)[idx] = r;
    }
}

// ---------------------------------------------------------------------------
extern "C" void kernel_launch(void* const* d_in, const int* in_sizes, int n_in,
                              void* d_out, int out_size) {
    const float* weight   = (const float*)d_in[0];
    const float* pre_s    = (const float*)d_in[1];
    const float* post_s   = (const float*)d_in[2];
    const float* pre_tr0  = (const float*)d_in[3];
    const float* post_tr0 = (const float*)d_in[4];
    float* out = (float*)d_out;

    cudaFuncSetAttribute(stdp_gemm_mma,
                         cudaFuncAttributeMaxDynamicSharedMemorySize, DSMEM_B);

    stdp_scanA<<<48 * CHUNKS, 256>>>(pre_s, post_s);
    stdp_scanC<<<48 * CHUNKS, 256>>>(pre_s, post_s, pre_tr0, post_tr0, out);

    dim3 grid(NIN / 128, NOUT / 128, 2 * KSPLIT);    // 8 x 4 x 8 = 256 CTAs
    stdp_gemm_mma<<<grid, 128, DSMEM_B>>>(weight, out);
}

// round 13
// speedup vs baseline: 1.8288x; 1.8288x over previous
#include <cuda_runtime.h>
#include <cuda_bf16.h>
#include <cstdint>

// ---------------------------------------------------------------------------
// STDP as two K=T*B GEMMs on mma.sync (bf16, fp32 accumulate).
// Scan parallelized over time via chunked linear-recurrence decomposition.
//   M1[o][i] = sum_k post_s[k][o] * pre_trH[k][i]   (post_s exact in bf16)
//   M2[o][i] = sum_k post_trH[k][o] * pre_s[k][i]   (pre_s  exact in bf16)
//   dw = LR_LTP*(1-w)*M1/B + LR_LTD*w*M2/B
// GEMM: 128-thr CTAs, warp tile 64x64, fragment double-buffering across kk.
// (R12's fused reduce reverted: it spilled the register-saturated GEMM.)
// ---------------------------------------------------------------------------

#define T_STEPS 100
#define BATCH   32
#define NIN     1024
#define NOUT    512
#define KTOT    3200                 // k = t*32 + b
#define KSPLIT  4
#define KPER    800                  // KTOT / KSPLIT
#define KC      80                   // k rows per smem stage (5 x k16)
#define NSTAGE  10                   // KPER / KC

#define CHUNKS  10
#define CLEN    10                   // T_STEPS / CHUNKS
#define NELEM   (BATCH * (NIN + NOUT))   // 49152 flat scan elements

#define DECAY   0.9512294245007141f  // expf(-1/20)
#define DECAY10 0.6065306597126334f  // expf(-0.5) = DECAY^10
#define LR_LTP  1e-4f
#define LR_LTD  (-1e-4f)

#define TILE_B  20480                // KC(80) rows x 256B (128 bf16 cols)
#define BUF_B   (2 * TILE_B)         // 40KB per stage (A tile + B tile)
#define DSMEM_B (2 * BUF_B)          // 80KB -> 2 CTAs/SM (160KB of 228KB)

// Scratch in natural [k][n] layout (__device__ globals; no allocs allowed)
__device__ __nv_bfloat16 g_preS [KTOT * NIN];    // pre_s  exact bf16
__device__ __nv_bfloat16 g_preH [KTOT * NIN];    // pre_tr bf16
__device__ __nv_bfloat16 g_postS[KTOT * NOUT];   // post_s exact bf16
__device__ __nv_bfloat16 g_postH[KTOT * NOUT];   // post_tr bf16
__device__ float g_f[CHUNKS * NELEM];            // per-chunk local finals
__device__ float g_m1[KSPLIT * NOUT * NIN];      // K-split partials
__device__ float g_m2[KSPLIT * NOUT * NIN];

// ---------------------------------------------------------------------------
__device__ __forceinline__ uint32_t smem_u32(const void* p) {
    uint32_t a;
    asm("{ .reg .u64 t; cvta.to.shared.u64 t, %1; cvt.u32.u64 %0, t; }"
        : "=r"(a) : "l"(p));
    return a;
}
__device__ __forceinline__ void cp_async16(uint32_t dst, const void* src) {
    asm volatile("cp.async.cg.shared.global [%0], [%1], 16;"
                 :: "r"(dst), "l"(src) : "memory");
}
__device__ __forceinline__ void cp_commit() {
    asm volatile("cp.async.commit_group;" ::: "memory");
}
template <int N> __device__ __forceinline__ void cp_wait() {
    asm volatile("cp.async.wait_group %0;" :: "n"(N) : "memory");
}
__device__ __forceinline__ void ldsm_x4_t(uint32_t& r0, uint32_t& r1,
                                          uint32_t& r2, uint32_t& r3, uint32_t a) {
    asm volatile("ldmatrix.sync.aligned.m8n8.x4.trans.shared.b16 {%0,%1,%2,%3}, [%4];"
                 : "=r"(r0), "=r"(r1), "=r"(r2), "=r"(r3) : "r"(a));
}
__device__ __forceinline__ void mma16816(float* c, const uint32_t* a,
                                         const uint32_t* b) {
    asm volatile(
        "mma.sync.aligned.m16n8k16.row.col.f32.bf16.bf16.f32 "
        "{%0,%1,%2,%3}, {%4,%5,%6,%7}, {%8,%9}, {%0,%1,%2,%3};"
        : "+f"(c[0]), "+f"(c[1]), "+f"(c[2]), "+f"(c[3])
        : "r"(a[0]), "r"(a[1]), "r"(a[2]), "r"(a[3]), "r"(b[0]), "r"(b[1]));
}
__device__ __forceinline__ uint32_t bits_bf2(__nv_bfloat162 v) {
    return *reinterpret_cast<uint32_t*>(&v);
}

// Shared (b, n4) mapping for the scan passes: 48 sub-blocks cover all elems.
struct ScanMap {
    const float* src;
    size_t nb;        // b*N + n4 within src
    size_t stride;    // 32*N
    int flat;         // flat element index (pre first, then post)
    int N, b, n4;
    bool isPre;
};
__device__ __forceinline__ ScanMap scan_map(int sub, int tid,
                                            const float* pre_s,
                                            const float* post_s) {
    ScanMap m;
    if (sub < 32) {
        m.isPre = true; m.N = NIN; m.b = sub; m.n4 = tid * 4;
        m.src = pre_s;
        m.flat = m.b * NIN + m.n4;
    } else {
        m.isPre = false; m.N = NOUT;
        m.b = (sub - 32) * 2 + (tid >> 7); m.n4 = (tid & 127) * 4;
        m.src = post_s;
        m.flat = BATCH * NIN + m.b * NOUT + m.n4;
    }
    m.nb = (size_t)m.b * m.N + m.n4;
    m.stride = (size_t)32 * m.N;
    return m;
}

// ---------------------------------------------------------------------------
// Pass A: per-chunk local scan (zero init) -> g_f[c][elem]; emit bf16 spikes.
// ---------------------------------------------------------------------------
__global__ void __launch_bounds__(256)
stdp_scanA(const float* __restrict__ pre_s, const float* __restrict__ post_s) {
    const int c   = blockIdx.x / 48;
    const int sub = blockIdx.x % 48;
    const ScanMap m = scan_map(sub, threadIdx.x, pre_s, post_s);
    __nv_bfloat16* gs = m.isPre ? g_preS : g_postS;

    float4 s[CLEN];
    #pragma unroll
    for (int u = 0; u < CLEN; u++)
        s[u] = *(const float4*)(m.src + (size_t)(c * CLEN + u) * m.stride + m.nb);

    float4 tr = make_float4(0.f, 0.f, 0.f, 0.f);
    #pragma unroll
    for (int u = 0; u < CLEN; u++) {
        tr.x = fmaf(tr.x, DECAY, s[u].x);
        tr.y = fmaf(tr.y, DECAY, s[u].y);
        tr.z = fmaf(tr.z, DECAY, s[u].z);
        tr.w = fmaf(tr.w, DECAY, s[u].w);

        uint2 sv;
        sv.x = bits_bf2(__float22bfloat162_rn(make_float2(s[u].x, s[u].y)));
        sv.y = bits_bf2(__float22bfloat162_rn(make_float2(s[u].z, s[u].w)));
        *(uint2*)(gs + (size_t)(c * CLEN + u) * m.stride + m.nb) = sv;
    }
    *(float4*)(g_f + (size_t)c * NELEM + m.flat) = tr;
}

// ---------------------------------------------------------------------------
// Pass C: recombine start from g_f (same fmaf order as a serial pass B ->
// bit-identical), re-scan the chunk, emit bf16 traces + final fp32 traces.
// ---------------------------------------------------------------------------
__global__ void __launch_bounds__(256)
stdp_scanC(const float* __restrict__ pre_s, const float* __restrict__ post_s,
           const float* __restrict__ pre0, const float* __restrict__ post0,
           float* __restrict__ out) {
    const int c   = blockIdx.x / 48;
    const int sub = blockIdx.x % 48;
    const ScanMap m = scan_map(sub, threadIdx.x, pre_s, post_s);
    __nv_bfloat16* gh = m.isPre ? g_preH : g_postH;

    float4 s[CLEN];
    #pragma unroll
    for (int u = 0; u < CLEN; u++)
        s[u] = *(const float4*)(m.src + (size_t)(c * CLEN + u) * m.stride + m.nb);

    // start(c) = fold of initial trace + chunk finals 0..c-1.
    // Loads are independent -> let the compiler unroll/pipeline them;
    // the fmaf chain order is unchanged (bit-identical result).
    float4 tr = m.isPre ? *(const float4*)(pre0 + m.nb)
                        : *(const float4*)(post0 + m.nb);
    #pragma unroll
    for (int j = 0; j < CHUNKS - 1; j++) {
        if (j < c) {
            float4 f = *(const float4*)(g_f + (size_t)j * NELEM + m.flat);
            tr.x = fmaf(tr.x, DECAY10, f.x);
            tr.y = fmaf(tr.y, DECAY10, f.y);
            tr.z = fmaf(tr.z, DECAY10, f.z);
            tr.w = fmaf(tr.w, DECAY10, f.w);
        }
    }

    #pragma unroll
    for (int u = 0; u < CLEN; u++) {
        tr.x = fmaf(tr.x, DECAY, s[u].x);
        tr.y = fmaf(tr.y, DECAY, s[u].y);
        tr.z = fmaf(tr.z, DECAY, s[u].z);
        tr.w = fmaf(tr.w, DECAY, s[u].w);

        uint2 hv;
        hv.x = bits_bf2(__float22bfloat162_rn(make_float2(tr.x, tr.y)));
        hv.y = bits_bf2(__float22bfloat162_rn(make_float2(tr.z, tr.w)));
        *(uint2*)(gh + (size_t)(c * CLEN + u) * m.stride + m.nb) = hv;
    }
    if (c == CHUNKS - 1) {
        const int outoff = NOUT * NIN + (m.isPre ? 0 : BATCH * NIN);
        *(float4*)(out + outoff + m.nb) = tr;
    }
}

// ---------------------------------------------------------------------------
// Kernel 2: mma.sync dual GEMM from [k][n] tiles via ldmatrix.trans.
//   blockIdx.z: z%2 = matrix select (0->M1, 1->M2), z/2 = K-slab.
// 128 threads, 4 warps of 64(o)x64(i). Fragment double-buffering: LDSMs for
// kk+1 are issued before the 32 MMAs of kk, hiding the smem latency.
// ---------------------------------------------------------------------------
__device__ __forceinline__ void load_tile(uint32_t sdst,
                                          const __nv_bfloat16* __restrict__ src,
                                          int N, int n0, int k0, int tid) {
    #pragma unroll
    for (int it = 0; it < 10; it++) {
        int idx = tid + it * 128;            // 1280 chunks of 16B
        int r = idx >> 4, c = idx & 15;
        uint32_t off = (uint32_t)(r * 256 + c * 16);
        uint32_t sw = off ^ (((uint32_t)r & 7) << 4);
        cp_async16(sdst + sw, src + (size_t)(k0 + r) * N + n0 + c * 8);
    }
}

#define LD_A(dst, buf, kk)                                               \
    { uint32_t koff_ = laneconst + (uint32_t)((kk) * 4096);              \
      _Pragma("unroll")                                                  \
      for (int mt_ = 0; mt_ < 4; mt_++) {                                \
        uint32_t off_ = koff_ + (uint32_t)((wm * 64 + mt_ * 16) * 2);    \
        ldsm_x4_t((dst)[mt_][0], (dst)[mt_][1], (dst)[mt_][2],           \
                  (dst)[mt_][3], (buf) + (off_ ^ xmask));                \
      } }

#define LD_B(dst, buf, kk)                                               \
    { uint32_t koff_ = laneconst + (uint32_t)((kk) * 4096) + TILE_B;     \
      _Pragma("unroll")                                                  \
      for (int ng_ = 0; ng_ < 4; ng_++) {                                \
        uint32_t off_ = koff_ + (uint32_t)((wn * 64 + ng_ * 16) * 2);    \
        uint32_t t0_, t1_, t2_, t3_;                                     \
        ldsm_x4_t(t0_, t1_, t2_, t3_, (buf) + (off_ ^ xmask));           \
        (dst)[ng_ * 2 + 0][0] = t0_; (dst)[ng_ * 2 + 1][0] = t1_;        \
        (dst)[ng_ * 2 + 0][1] = t2_; (dst)[ng_ * 2 + 1][1] = t3_;        \
      } }

__global__ void __launch_bounds__(128, 2)
stdp_gemm_mma() {
    extern __shared__ __align__(1024) char dsm[];
    const uint32_t sb = smem_u32(dsm);

    const int tid  = threadIdx.x;
    const int lane = tid & 31;
    const int wid  = tid >> 5;
    const int wm   = wid >> 1;           // 0..1 -> 64 o-rows
    const int wn   = wid & 1;            // 0..1 -> 64 i-cols
    const int i0   = blockIdx.x * 128;
    const int o0   = blockIdx.y * 128;
    const int gsel = blockIdx.z % 2;
    const int ksl  = blockIdx.z / 2;
    const int kb   = ksl * KPER;

    // M1: A=post_s (exact), B=pre_trH.   M2: A=post_trH, B=pre_s (exact).
    const __nv_bfloat16* Ap = gsel ? g_postH : g_postS;   // [k][NOUT]
    const __nv_bfloat16* Bp = gsel ? g_preS  : g_preH;    // [k][NIN]

    float acc[4][8][4];
    #pragma unroll
    for (int mt = 0; mt < 4; mt++)
        #pragma unroll
        for (int nt = 0; nt < 8; nt++)
            #pragma unroll
            for (int r = 0; r < 4; r++) acc[mt][nt][r] = 0.f;

    load_tile(sb + 0 * TILE_B, Ap, NOUT, o0, kb, tid);
    load_tile(sb + 1 * TILE_B, Bp, NIN,  i0, kb, tid);
    cp_commit();

    // per-lane ldmatrix.trans addressing:
    // row = kk*16 + (lane>>4)*8 + (lane&7); colb = col*2 + ((lane>>3)&1)*16
    const uint32_t laneconst = (uint32_t)(((lane >> 4) * 8 + (lane & 7)) * 256
                                          + ((lane >> 3) & 1) * 16);
    const uint32_t xmask = (uint32_t)((lane & 7) << 4);

    uint32_t afr[2][4][4];               // double-buffered A fragments
    uint32_t bfr[2][8][2];               // double-buffered B fragments

    #pragma unroll 1
    for (int s = 0; s < NSTAGE; s++) {
        if (s + 1 < NSTAGE) {
            uint32_t nbuf = sb + ((s + 1) & 1) * BUF_B;
            int k0 = kb + (s + 1) * KC;
            load_tile(nbuf + 0 * TILE_B, Ap, NOUT, o0, k0, tid);
            load_tile(nbuf + 1 * TILE_B, Bp, NIN,  i0, k0, tid);
            cp_commit();
            cp_wait<1>();
        } else {
            cp_wait<0>();
        }
        __syncthreads();

        const uint32_t buf = sb + (s & 1) * BUF_B;
        LD_A(afr[0], buf, 0);
        LD_B(bfr[0], buf, 0);
        #pragma unroll
        for (int kk = 0; kk < 5; kk++) {
            const int cur = kk & 1;
            const int nxt = cur ^ 1;
            if (kk < 4) {                 // prefetch kk+1 before MMAs of kk
                LD_A(afr[nxt], buf, kk + 1);
                LD_B(bfr[nxt], buf, kk + 1);
            }
            #pragma unroll
            for (int mt = 0; mt < 4; mt++)
                #pragma unroll
                for (int nt = 0; nt < 8; nt++)
                    mma16816(acc[mt][nt], afr[cur][mt], bfr[cur][nt]);
        }
        __syncthreads();
    }

    // epilogue: direct fp32 stores of this slab's partials
    float* gdst = (gsel ? g_m2 : g_m1) + (size_t)ksl * (NOUT * NIN);
    const int rr = lane >> 2;
    const int cc = (lane & 3) * 2;
    #pragma unroll
    for (int mt = 0; mt < 4; mt++) {
        #pragma unroll
        for (int nt = 0; nt < 8; nt++) {
            int row = o0 + wm * 64 + mt * 16 + rr;
            int col = i0 + wn * 64 + nt * 8 + cc;
            float2 v0 = make_float2(acc[mt][nt][0], acc[mt][nt][1]);
            float2 v1 = make_float2(acc[mt][nt][2], acc[mt][nt][3]);
            *(float2*)&gdst[(size_t)row * NIN + col]       = v0;
            *(float2*)&gdst[(size_t)(row + 8) * NIN + col] = v1;
        }
    }
}

// ---------------------------------------------------------------------------
// Kernel 3: reduce K-split slabs + soft-bound weight scaling.
// float2 granularity, 262144 threads -> 2x TLP of the float4 version
// (it was latency-bound: issue 6.9%, DRAM 31.8%). Same per-element
// arithmetic order -> bit-identical.
// ---------------------------------------------------------------------------
__global__ void __launch_bounds__(256)
stdp_final(const float* __restrict__ w, float* __restrict__ out) {
    const int idx = blockIdx.x * blockDim.x + threadIdx.x;   // float2 index
    const int n2 = NOUT * NIN / 2;
    if (idx >= n2) return;

    float2 m1 = make_float2(0.f, 0.f);
    float2 m2 = make_float2(0.f, 0.f);
    #pragma unroll
    for (int z = 0; z < KSPLIT; z++) {
        float2 a = ((const float2*)g_m1)[(size_t)z * n2 + idx];
        float2 b = ((const float2*)g_m2)[(size_t)z * n2 + idx];
        m1.x += a.x; m1.y += a.y;
        m2.x += b.x; m2.y += b.y;
    }
    const float2 wv = ((const float2*)w)[idx];
    const float sp = LR_LTP / (float)BATCH;
    const float sd = LR_LTD / (float)BATCH;
    float2 r;
    r.x = sp * (1.f - wv.x) * m1.x + sd * wv.x * m2.x;
    r.y = sp * (1.f - wv.y) * m1.y + sd * wv.y * m2.y;
    ((float2*)out)[idx] = r;
}

// ---------------------------------------------------------------------------
extern "C" void kernel_launch(void* const* d_in, const int* in_sizes, int n_in,
                              void* d_out, int out_size) {
    const float* weight   = (const float*)d_in[0];
    const float* pre_s    = (const float*)d_in[1];
    const float* post_s   = (const float*)d_in[2];
    const float* pre_tr0  = (const float*)d_in[3];
    const float* post_tr0 = (const float*)d_in[4];
    float* out = (float*)d_out;

    cudaFuncSetAttribute(stdp_gemm_mma,
                         cudaFuncAttributeMaxDynamicSharedMemorySize, DSMEM_B);

    stdp_scanA<<<48 * CHUNKS, 256>>>(pre_s, post_s);
    stdp_scanC<<<48 * CHUNKS, 256>>>(pre_s, post_s, pre_tr0, post_tr0, out);

    dim3 grid(NIN / 128, NOUT / 128, 2 * KSPLIT);    // 8 x 4 x 8 = 256 CTAs
    stdp_gemm_mma<<<grid, 128, DSMEM_B>>>();

    stdp_final<<<(NOUT * NIN / 2 + 255) / 256, 256>>>(weight, out);
}

// round 14
// speedup vs baseline: 1.8852x; 1.0308x over previous
#include <cuda_runtime.h>
#include <cuda_bf16.h>
#include <cstdint>

// ---------------------------------------------------------------------------
// STDP as two K=T*B GEMMs on mma.sync (bf16, fp32 accumulate).
// Scan parallelized over time via chunked linear-recurrence decomposition.
//   M1[o][i] = sum_k post_s[k][o] * pre_trH[k][i]   (post_s exact in bf16)
//   M2[o][i] = sum_k post_trH[k][o] * pre_s[k][i]   (pre_s  exact in bf16)
//   dw = LR_LTP*(1-w)*M1/B + LR_LTD*w*M2/B
// GEMM: 128-thr CTAs, warp tile 64x64, fragment double-buffering across kk,
// single barrier per stage, cp.async issue spread across the kk loop.
// ---------------------------------------------------------------------------

#define T_STEPS 100
#define BATCH   32
#define NIN     1024
#define NOUT    512
#define KTOT    3200                 // k = t*32 + b
#define KSPLIT  4
#define KPER    800                  // KTOT / KSPLIT
#define KC      80                   // k rows per smem stage (5 x k16)
#define NSTAGE  10                   // KPER / KC

#define CHUNKS  10
#define CLEN    10                   // T_STEPS / CHUNKS
#define NELEM   (BATCH * (NIN + NOUT))   // 49152 flat scan elements

#define DECAY   0.9512294245007141f  // expf(-1/20)
#define DECAY10 0.6065306597126334f  // expf(-0.5) = DECAY^10
#define LR_LTP  1e-4f
#define LR_LTD  (-1e-4f)

#define TILE_B  20480                // KC(80) rows x 256B (128 bf16 cols)
#define BUF_B   (2 * TILE_B)         // 40KB per stage (A tile + B tile)
#define DSMEM_B (2 * BUF_B)          // 80KB -> 2 CTAs/SM (160KB of 228KB)

// Scratch in natural [k][n] layout (__device__ globals; no allocs allowed)
__device__ __nv_bfloat16 g_preS [KTOT * NIN];    // pre_s  exact bf16
__device__ __nv_bfloat16 g_preH [KTOT * NIN];    // pre_tr bf16
__device__ __nv_bfloat16 g_postS[KTOT * NOUT];   // post_s exact bf16
__device__ __nv_bfloat16 g_postH[KTOT * NOUT];   // post_tr bf16
__device__ float g_f[CHUNKS * NELEM];            // per-chunk local finals
__device__ float g_m1[KSPLIT * NOUT * NIN];      // K-split partials
__device__ float g_m2[KSPLIT * NOUT * NIN];

// ---------------------------------------------------------------------------
__device__ __forceinline__ uint32_t smem_u32(const void* p) {
    uint32_t a;
    asm("{ .reg .u64 t; cvta.to.shared.u64 t, %1; cvt.u32.u64 %0, t; }"
        : "=r"(a) : "l"(p));
    return a;
}
__device__ __forceinline__ void cp_async16(uint32_t dst, const void* src) {
    asm volatile("cp.async.cg.shared.global [%0], [%1], 16;"
                 :: "r"(dst), "l"(src) : "memory");
}
__device__ __forceinline__ void cp_commit() {
    asm volatile("cp.async.commit_group;" ::: "memory");
}
template <int N> __device__ __forceinline__ void cp_wait() {
    asm volatile("cp.async.wait_group %0;" :: "n"(N) : "memory");
}
__device__ __forceinline__ void ldsm_x4_t(uint32_t& r0, uint32_t& r1,
                                          uint32_t& r2, uint32_t& r3, uint32_t a) {
    asm volatile("ldmatrix.sync.aligned.m8n8.x4.trans.shared.b16 {%0,%1,%2,%3}, [%4];"
                 : "=r"(r0), "=r"(r1), "=r"(r2), "=r"(r3) : "r"(a));
}
__device__ __forceinline__ void mma16816(float* c, const uint32_t* a,
                                         const uint32_t* b) {
    asm volatile(
        "mma.sync.aligned.m16n8k16.row.col.f32.bf16.bf16.f32 "
        "{%0,%1,%2,%3}, {%4,%5,%6,%7}, {%8,%9}, {%0,%1,%2,%3};"
        : "+f"(c[0]), "+f"(c[1]), "+f"(c[2]), "+f"(c[3])
        : "r"(a[0]), "r"(a[1]), "r"(a[2]), "r"(a[3]), "r"(b[0]), "r"(b[1]));
}
__device__ __forceinline__ uint32_t bits_bf2(__nv_bfloat162 v) {
    return *reinterpret_cast<uint32_t*>(&v);
}

// Shared (b, n4) mapping for the scan passes: 48 sub-blocks cover all elems.
struct ScanMap {
    const float* src;
    size_t nb;        // b*N + n4 within src
    size_t stride;    // 32*N
    int flat;         // flat element index (pre first, then post)
    int N, b, n4;
    bool isPre;
};
__device__ __forceinline__ ScanMap scan_map(int sub, int tid,
                                            const float* pre_s,
                                            const float* post_s) {
    ScanMap m;
    if (sub < 32) {
        m.isPre = true; m.N = NIN; m.b = sub; m.n4 = tid * 4;
        m.src = pre_s;
        m.flat = m.b * NIN + m.n4;
    } else {
        m.isPre = false; m.N = NOUT;
        m.b = (sub - 32) * 2 + (tid >> 7); m.n4 = (tid & 127) * 4;
        m.src = post_s;
        m.flat = BATCH * NIN + m.b * NOUT + m.n4;
    }
    m.nb = (size_t)m.b * m.N + m.n4;
    m.stride = (size_t)32 * m.N;
    return m;
}

// ---------------------------------------------------------------------------
// Pass A: per-chunk local scan (zero init) -> g_f[c][elem]; emit bf16 spikes.
// ---------------------------------------------------------------------------
__global__ void __launch_bounds__(256)
stdp_scanA(const float* __restrict__ pre_s, const float* __restrict__ post_s) {
    const int c   = blockIdx.x / 48;
    const int sub = blockIdx.x % 48;
    const ScanMap m = scan_map(sub, threadIdx.x, pre_s, post_s);
    __nv_bfloat16* gs = m.isPre ? g_preS : g_postS;

    float4 s[CLEN];
    #pragma unroll
    for (int u = 0; u < CLEN; u++)
        s[u] = *(const float4*)(m.src + (size_t)(c * CLEN + u) * m.stride + m.nb);

    float4 tr = make_float4(0.f, 0.f, 0.f, 0.f);
    #pragma unroll
    for (int u = 0; u < CLEN; u++) {
        tr.x = fmaf(tr.x, DECAY, s[u].x);
        tr.y = fmaf(tr.y, DECAY, s[u].y);
        tr.z = fmaf(tr.z, DECAY, s[u].z);
        tr.w = fmaf(tr.w, DECAY, s[u].w);

        uint2 sv;
        sv.x = bits_bf2(__float22bfloat162_rn(make_float2(s[u].x, s[u].y)));
        sv.y = bits_bf2(__float22bfloat162_rn(make_float2(s[u].z, s[u].w)));
        *(uint2*)(gs + (size_t)(c * CLEN + u) * m.stride + m.nb) = sv;
    }
    *(float4*)(g_f + (size_t)c * NELEM + m.flat) = tr;
}

// ---------------------------------------------------------------------------
// Pass C: recombine start from g_f (same fmaf order as a serial pass B ->
// bit-identical), re-scan the chunk reading the bf16 spikes (0/1 -> exact),
// emit bf16 traces + final fp32 traces.
// ---------------------------------------------------------------------------
__global__ void __launch_bounds__(256)
stdp_scanC(const float* __restrict__ pre_s, const float* __restrict__ post_s,
           const float* __restrict__ pre0, const float* __restrict__ post0,
           float* __restrict__ out) {
    const int c   = blockIdx.x / 48;
    const int sub = blockIdx.x % 48;
    const ScanMap m = scan_map(sub, threadIdx.x, pre_s, post_s);
    const __nv_bfloat16* gs = m.isPre ? g_preS : g_postS;
    __nv_bfloat16* gh = m.isPre ? g_preH : g_postH;

    // spikes from the bf16 copy (exact values, half the read traffic)
    float4 s[CLEN];
    #pragma unroll
    for (int u = 0; u < CLEN; u++) {
        uint2 sv = *(const uint2*)(gs + (size_t)(c * CLEN + u) * m.stride + m.nb);
        __nv_bfloat162 b0 = *reinterpret_cast<__nv_bfloat162*>(&sv.x);
        __nv_bfloat162 b1 = *reinterpret_cast<__nv_bfloat162*>(&sv.y);
        s[u].x = __bfloat162float(__low2bfloat16(b0));
        s[u].y = __bfloat162float(__high2bfloat16(b0));
        s[u].z = __bfloat162float(__low2bfloat16(b1));
        s[u].w = __bfloat162float(__high2bfloat16(b1));
    }

    // start(c) = fold of initial trace + chunk finals 0..c-1 (order preserved)
    float4 tr = m.isPre ? *(const float4*)(pre0 + m.nb)
                        : *(const float4*)(post0 + m.nb);
    #pragma unroll
    for (int j = 0; j < CHUNKS - 1; j++) {
        if (j < c) {
            float4 f = *(const float4*)(g_f + (size_t)j * NELEM + m.flat);
            tr.x = fmaf(tr.x, DECAY10, f.x);
            tr.y = fmaf(tr.y, DECAY10, f.y);
            tr.z = fmaf(tr.z, DECAY10, f.z);
            tr.w = fmaf(tr.w, DECAY10, f.w);
        }
    }

    #pragma unroll
    for (int u = 0; u < CLEN; u++) {
        tr.x = fmaf(tr.x, DECAY, s[u].x);
        tr.y = fmaf(tr.y, DECAY, s[u].y);
        tr.z = fmaf(tr.z, DECAY, s[u].z);
        tr.w = fmaf(tr.w, DECAY, s[u].w);

        uint2 hv;
        hv.x = bits_bf2(__float22bfloat162_rn(make_float2(tr.x, tr.y)));
        hv.y = bits_bf2(__float22bfloat162_rn(make_float2(tr.z, tr.w)));
        *(uint2*)(gh + (size_t)(c * CLEN + u) * m.stride + m.nb) = hv;
    }
    if (c == CHUNKS - 1) {
        const int outoff = NOUT * NIN + (m.isPre ? 0 : BATCH * NIN);
        *(float4*)(out + outoff + m.nb) = tr;
    }
}

// ---------------------------------------------------------------------------
// Kernel 2: mma.sync dual GEMM from [k][n] tiles via ldmatrix.trans.
//   blockIdx.z: z%2 = matrix select (0->M1, 1->M2), z/2 = K-slab.
// 128 threads, 4 warps of 64(o)x64(i). Fragment double-buffering across kk;
// ONE barrier per stage; next-stage cp.async issue spread across the kk loop.
// ---------------------------------------------------------------------------
__device__ __forceinline__ void load_tile_part(uint32_t sdst,
                                               const __nv_bfloat16* __restrict__ src,
                                               int N, int n0, int k0, int tid,
                                               int it0) {
    #pragma unroll
    for (int it = it0; it < it0 + 2; it++) {
        int idx = tid + it * 128;            // of 1280 chunks of 16B
        int r = idx >> 4, c = idx & 15;
        uint32_t off = (uint32_t)(r * 256 + c * 16);
        uint32_t sw = off ^ (((uint32_t)r & 7) << 4);
        cp_async16(sdst + sw, src + (size_t)(k0 + r) * N + n0 + c * 8);
    }
}
__device__ __forceinline__ void load_tile(uint32_t sdst,
                                          const __nv_bfloat16* __restrict__ src,
                                          int N, int n0, int k0, int tid) {
    #pragma unroll
    for (int it = 0; it < 10; it += 2)
        load_tile_part(sdst, src, N, n0, k0, tid, it);
}

#define LD_A(dst, buf, kk)                                               \
    { uint32_t koff_ = laneconst + (uint32_t)((kk) * 4096);              \
      _Pragma("unroll")                                                  \
      for (int mt_ = 0; mt_ < 4; mt_++) {                                \
        uint32_t off_ = koff_ + (uint32_t)((wm * 64 + mt_ * 16) * 2);    \
        ldsm_x4_t((dst)[mt_][0], (dst)[mt_][1], (dst)[mt_][2],           \
                  (dst)[mt_][3], (buf) + (off_ ^ xmask));                \
      } }

#define LD_B(dst, buf, kk)                                               \
    { uint32_t koff_ = laneconst + (uint32_t)((kk) * 4096) + TILE_B;     \
      _Pragma("unroll")                                                  \
      for (int ng_ = 0; ng_ < 4; ng_++) {                                \
        uint32_t off_ = koff_ + (uint32_t)((wn * 64 + ng_ * 16) * 2);    \
        uint32_t t0_, t1_, t2_, t3_;                                     \
        ldsm_x4_t(t0_, t1_, t2_, t3_, (buf) + (off_ ^ xmask));           \
        (dst)[ng_ * 2 + 0][0] = t0_; (dst)[ng_ * 2 + 1][0] = t1_;        \
        (dst)[ng_ * 2 + 0][1] = t2_; (dst)[ng_ * 2 + 1][1] = t3_;        \
      } }

__global__ void __launch_bounds__(128, 2)
stdp_gemm_mma() {
    extern __shared__ __align__(1024) char dsm[];
    const uint32_t sb = smem_u32(dsm);

    const int tid  = threadIdx.x;
    const int lane = tid & 31;
    const int wid  = tid >> 5;
    const int wm   = wid >> 1;           // 0..1 -> 64 o-rows
    const int wn   = wid & 1;            // 0..1 -> 64 i-cols
    const int i0   = blockIdx.x * 128;
    const int o0   = blockIdx.y * 128;
    const int gsel = blockIdx.z % 2;
    const int ksl  = blockIdx.z / 2;
    const int kb   = ksl * KPER;

    // M1: A=post_s (exact), B=pre_trH.   M2: A=post_trH, B=pre_s (exact).
    const __nv_bfloat16* Ap = gsel ? g_postH : g_postS;   // [k][NOUT]
    const __nv_bfloat16* Bp = gsel ? g_preS  : g_preH;    // [k][NIN]

    float acc[4][8][4];
    #pragma unroll
    for (int mt = 0; mt < 4; mt++)
        #pragma unroll
        for (int nt = 0; nt < 8; nt++)
            #pragma unroll
            for (int r = 0; r < 4; r++) acc[mt][nt][r] = 0.f;

    // prologue: full stage-0 load, committed as one group
    load_tile(sb + 0 * TILE_B, Ap, NOUT, o0, kb, tid);
    load_tile(sb + 1 * TILE_B, Bp, NIN,  i0, kb, tid);
    cp_commit();

    // per-lane ldmatrix.trans addressing:
    // row = kk*16 + (lane>>4)*8 + (lane&7); colb = col*2 + ((lane>>3)&1)*16
    const uint32_t laneconst = (uint32_t)(((lane >> 4) * 8 + (lane & 7)) * 256
                                          + ((lane >> 3) & 1) * 16);
    const uint32_t xmask = (uint32_t)((lane & 7) << 4);

    uint32_t afr[2][4][4];               // double-buffered A fragments
    uint32_t bfr[2][8][2];               // double-buffered B fragments

    #pragma unroll 1
    for (int s = 0; s < NSTAGE; s++) {
        cp_wait<0>();                    // stage-s group (committed last iter)
        __syncthreads();                 // data visible + old buffer free

        const uint32_t buf  = sb + (s & 1) * BUF_B;
        const uint32_t nbuf = sb + ((s + 1) & 1) * BUF_B;
        const int k1 = kb + (s + 1) * KC;
        const bool more = (s + 1 < NSTAGE);

        LD_A(afr[0], buf, 0);
        LD_B(bfr[0], buf, 0);
        #pragma unroll
        for (int kk = 0; kk < 5; kk++) {
            if (more) {                  // spread next-stage LDGSTS issue
                load_tile_part(nbuf + 0 * TILE_B, Ap, NOUT, o0, k1, tid, kk * 2);
                load_tile_part(nbuf + 1 * TILE_B, Bp, NIN,  i0, k1, tid, kk * 2);
            }
            const int cur = kk & 1;
            const int nxt = cur ^ 1;
            if (kk < 4) {                // prefetch kk+1 fragments
                LD_A(afr[nxt], buf, kk + 1);
                LD_B(bfr[nxt], buf, kk + 1);
            }
            #pragma unroll
            for (int mt = 0; mt < 4; mt++)
                #pragma unroll
                for (int nt = 0; nt < 8; nt++)
                    mma16816(acc[mt][nt], afr[cur][mt], bfr[cur][nt]);
        }
        if (more) cp_commit();
    }

    // epilogue: direct fp32 stores of this slab's partials
    float* gdst = (gsel ? g_m2 : g_m1) + (size_t)ksl * (NOUT * NIN);
    const int rr = lane >> 2;
    const int cc = (lane & 3) * 2;
    #pragma unroll
    for (int mt = 0; mt < 4; mt++) {
        #pragma unroll
        for (int nt = 0; nt < 8; nt++) {
            int row = o0 + wm * 64 + mt * 16 + rr;
            int col = i0 + wn * 64 + nt * 8 + cc;
            float2 v0 = make_float2(acc[mt][nt][0], acc[mt][nt][1]);
            float2 v1 = make_float2(acc[mt][nt][2], acc[mt][nt][3]);
            *(float2*)&gdst[(size_t)row * NIN + col]       = v0;
            *(float2*)&gdst[(size_t)(row + 8) * NIN + col] = v1;
        }
    }
}

// ---------------------------------------------------------------------------
// Kernel 3: reduce K-split slabs + soft-bound weight scaling.
// ---------------------------------------------------------------------------
__global__ void __launch_bounds__(256)
stdp_final(const float* __restrict__ w, float* __restrict__ out) {
    const int idx = blockIdx.x * blockDim.x + threadIdx.x;   // float2 index
    const int n2 = NOUT * NIN / 2;
    if (idx >= n2) return;

    float2 m1 = make_float2(0.f, 0.f);
    float2 m2 = make_float2(0.f, 0.f);
    #pragma unroll
    for (int z = 0; z < KSPLIT; z++) {
        float2 a = ((const float2*)g_m1)[(size_t)z * n2 + idx];
        float2 b = ((const float2*)g_m2)[(size_t)z * n2 + idx];
        m1.x += a.x; m1.y += a.y;
        m2.x += b.x; m2.y += b.y;
    }
    const float2 wv = ((const float2*)w)[idx];
    const float sp = LR_LTP / (float)BATCH;
    const float sd = LR_LTD / (float)BATCH;
    float2 r;
    r.x = sp * (1.f - wv.x) * m1.x + sd * wv.x * m2.x;
    r.y = sp * (1.f - wv.y) * m1.y + sd * wv.y * m2.y;
    ((float2*)out)[idx] = r;
}

// ---------------------------------------------------------------------------
extern "C" void kernel_launch(void* const* d_in, const int* in_sizes, int n_in,
                              void* d_out, int out_size) {
    const float* weight   = (const float*)d_in[0];
    const float* pre_s    = (const float*)d_in[1];
    const float* post_s   = (const float*)d_in[2];
    const float* pre_tr0  = (const float*)d_in[3];
    const float* post_tr0 = (const float*)d_in[4];
    float* out = (float*)d_out;

    cudaFuncSetAttribute(stdp_gemm_mma,
                         cudaFuncAttributeMaxDynamicSharedMemorySize, DSMEM_B);

    stdp_scanA<<<48 * CHUNKS, 256>>>(pre_s, post_s);
    stdp_scanC<<<48 * CHUNKS, 256>>>(pre_s, post_s, pre_tr0, post_tr0, out);

    dim3 grid(NIN / 128, NOUT / 128, 2 * KSPLIT);    // 8 x 4 x 8 = 256 CTAs
    stdp_gemm_mma<<<grid, 128, DSMEM_B>>>();

    stdp_final<<<(NOUT * NIN / 2 + 255) / 256, 256>>>(weight, out);
}